// round 8
// baseline (speedup 1.0000x reference)
#include <cuda_runtime.h>
#include <stdint.h>

#define MDIM  41
#define HALF  20
#define NPAIR 1261                 // (m,n) pairs with |m+n| <= 20
#define NTRIP (NPAIR * MDIM)       // 51701 triplets
#define BATCH 128
#define TPB   256
#define JPT   8                    // float4-pairs per thread
#define JBLK  (TPB * JPT)          // 2048 j per block
#define NJ    25850                // float4 pairs per (b, mode)
#define MAXP  104                  // pairs spanned by a 4098-t window (<=102)
#define NCPLX (26470912LL)         // 128*2*2*51701 (real-parts buffer, floats)
#define NFLT  (52941824LL)         // full interleaved-complex float count

__device__ __forceinline__ int pair_base(int i) {
    return (i <= HALF) ? (i * (i + 41)) >> 1
                       : 651 + (((102 - i) * (i - 21)) >> 1);
}

__device__ __forceinline__ void decode_pair(int p, int& im, int& in_, int& imn) {
    int i;
    if (p < 651) {
        i = (int)((-41.0f + __fsqrt_rn(1681.0f + 8.0f * (float)p)) * 0.5f);
    } else {
        float q = (float)(p - 651);
        i = 21 + (int)((81.0f - __fsqrt_rn(6561.0f - 8.0f * q)) * 0.5f);
    }
    if (i < 0) i = 0;
    if (i > 40) i = 40;
    while (i < 40 && pair_base(i + 1) <= p) i++;
    while (i > 0 && pair_base(i) > p) i--;
    int m   = i - HALF;
    int off = p - pair_base(i);
    int nlo = (m > 0) ? -HALF : -HALF - m;
    int n   = nlo + off;
    im  = i;
    in_ = n + HALF;
    imn = m + n + HALF;
}

// compute E1 (both modes) for pair p from sE
__device__ __forceinline__ float4 make_e1(const float4* sE, int p) {
    int im, in_, imn;
    decode_pair(p, im, in_, imn);
    float4 a = sE[im], c = sE[in_], d = sE[imn];
    float abx0 = a.x*c.x - a.y*c.y;
    float aby0 = a.x*c.y + a.y*c.x;
    float abx1 = a.z*c.z - a.w*c.w;
    float aby1 = a.z*c.w + a.w*c.z;
    return make_float4(abx0*d.x + aby0*d.y,   // e1x0
                       aby0*d.x - abx0*d.y,   // e1y0
                       abx1*d.z + aby1*d.w,   // e1x1
                       aby1*d.z - abx1*d.w);  // e1y1
}

// ---------------- MODE 1: real-parts-only layout (primary) ----------------
// out as float2: element (b*2+nm)*NTRIP + t = {feat1.re, feat2.re}
// nm0 float4 j packs t = {2j, 2j+1}   at float4 idx b*NTRIP + j
// nm1 float4 j packs t = {2j+1, 2j+2} at float4 idx b*NTRIP + 25851 + j
// leftovers: nm0 t=51700, nm1 t=0 (scalar float2, block 0)
__global__ void __launch_bounds__(TPB)
sofeat_v4_kernel(const float* __restrict__ Er,
                 const float* __restrict__ Ei,
                 float4* __restrict__ out4)
{
    __shared__ float4 sE[MDIM];      // (re0, im0, re1, im1)
    __shared__ float4 sT[MDIM];      // (t1, t2x, t2y, 0)
    __shared__ float4 sE1[MAXP];

    const int tid  = threadIdx.x;
    const int b    = blockIdx.y;
    const int j_lo = blockIdx.x * JBLK;
    const int j_hi = (j_lo + JBLK < NJ) ? j_lo + JBLK : NJ;
    const int p_lo = (2 * j_lo) / MDIM;
    const int np   = (2 * j_hi) / MDIM - p_lo + 1;   // covers t up to 2*j_hi

    // phase 0: E[b], packed terms
    if (tid < MDIM) {
        const float* er = Er + (size_t)b * (MDIM * 2);
        const float* ei = Ei + (size_t)b * (MDIM * 2);
        int i = tid, jm = 40 - tid;
        float4 e = make_float4(er[2*i], ei[2*i], er[2*i+1], ei[2*i+1]);
        float4 q = make_float4(er[2*jm], ei[2*jm], er[2*jm+1], ei[2*jm+1]);
        sE[i] = e;
        float t1  = e.x*e.x + e.y*e.y + e.z*e.z + e.w*e.w;
        float t2x = e.x*q.x - e.y*q.y + e.z*q.z - e.w*q.w;
        float t2y = e.x*q.y + e.y*q.x + e.z*q.w + e.w*q.z;
        sT[i] = make_float4(t1, t2x, t2y, 0.f);
    }
    __syncthreads();

    // phase 1: E1 per pair in window
    if (tid < np && p_lo + tid < NPAIR)
        sE1[tid] = make_e1(sE, p_lo + tid);

    // leftovers (block 0 only): nm1 t=0 and nm0 t=51700
    if (blockIdx.x == 0 && tid >= 64 && tid < 66) {
        float2* out2 = reinterpret_cast<float2*>(out4);
        if (tid == 64) {
            float4 e1 = make_e1(sE, 0);           // p=0, k=0
            float4 T  = sT[0];
            out2[(size_t)(2*b + 1) * NTRIP] =
                make_float2(e1.z * T.x, e1.z*T.y + e1.w*T.z);
        } else {
            float4 e1 = make_e1(sE, NPAIR - 1);   // p=1260, k=40
            float4 T  = sT[40];
            out2[(size_t)(2*b) * NTRIP + (NTRIP - 1)] =
                make_float2(e1.x * T.x, e1.x*T.y + e1.y*T.z);
        }
    }
    __syncthreads();

    const size_t o0 = (size_t)b * NTRIP;             // nm0 float4 base
    const size_t o1 = (size_t)b * NTRIP + 25851;     // nm1 float4 base

    #pragma unroll
    for (int jj = 0; jj < JPT; jj++) {
        const int j = j_lo + jj * TPB + tid;
        if (j >= j_hi) break;

        const int t0 = 2 * j;
        unsigned p0 = (unsigned)t0 / MDIM;            // magic-mul
        int k0 = t0 - (int)p0 * MDIM;
        int k1 = k0 + 1; unsigned p1 = p0; if (k1 == MDIM) { k1 = 0; p1++; }
        int k2 = k1 + 1; unsigned p2 = p1; if (k2 == MDIM) { k2 = 0; p2++; }

        const float4 T0 = sT[k0], T1 = sT[k1], T2 = sT[k2];
        const float4 ea = sE1[p0 - (unsigned)p_lo];
        const float4 eb = sE1[p1 - (unsigned)p_lo];
        const float4 ec = sE1[p2 - (unsigned)p_lo];

        float4 v0;   // nm0: t0 (ea), t1 (eb)
        v0.x = ea.x * T0.x;
        v0.y = ea.x * T0.y + ea.y * T0.z;
        v0.z = eb.x * T1.x;
        v0.w = eb.x * T1.y + eb.y * T1.z;

        float4 v1;   // nm1: t1 (eb), t2 (ec)
        v1.x = eb.z * T1.x;
        v1.y = eb.z * T1.y + eb.w * T1.z;
        v1.z = ec.z * T2.x;
        v1.w = ec.z * T2.y + ec.w * T2.z;

        out4[o0 + j] = v0;
        out4[o1 + j] = v1;
    }
}

// ---------------- MODE 0 fallback: interleaved complex ----------------
#define TPT   4
#define TBLK  (TPB * TPT)
#define MAXPF 28
__global__ void __launch_bounds__(TPB)
sofeat_full_kernel(const float* __restrict__ Er,
                   const float* __restrict__ Ei,
                   float* __restrict__ out,
                   size_t cap_f)
{
    __shared__ float4 sE[MDIM];
    __shared__ float  sT1[MDIM];
    __shared__ float2 sT2[MDIM];
    __shared__ float4 sE1[MAXPF];

    const int tid  = threadIdx.x;
    const int b    = blockIdx.y;
    const int t_lo = blockIdx.x * TBLK;
    const int t_hi = (t_lo + TBLK < NTRIP) ? t_lo + TBLK : NTRIP;
    const int p_lo = t_lo / MDIM;
    const int np   = (t_hi - 1) / MDIM - p_lo + 1;

    if (tid < MDIM) {
        const float* er = Er + (size_t)b * (MDIM * 2);
        const float* ei = Ei + (size_t)b * (MDIM * 2);
        int i = tid, jm = 40 - tid;
        float4 e = make_float4(er[2*i], ei[2*i], er[2*i+1], ei[2*i+1]);
        float4 q = make_float4(er[2*jm], ei[2*jm], er[2*jm+1], ei[2*jm+1]);
        sE[i]  = e;
        sT1[i] = e.x*e.x + e.y*e.y + e.z*e.z + e.w*e.w;
        float2 t2;
        t2.x = e.x*q.x - e.y*q.y + e.z*q.z - e.w*q.w;
        t2.y = e.x*q.y + e.y*q.x + e.z*q.w + e.w*q.z;
        sT2[i] = t2;
    }
    __syncthreads();

    if (tid < np)
        sE1[tid] = make_e1(sE, p_lo + tid);
    __syncthreads();

    int t = t_lo + tid;
    #pragma unroll
    for (int jj = 0; jj < TPT; jj++, t += TPB) {
        if (t >= t_hi) break;
        const unsigned p  = (unsigned)t / MDIM;
        const int      kk = t - (int)p * MDIM;
        const float4 e1 = sE1[p - (unsigned)p_lo];
        const float  t1 = sT1[kk];
        const float2 t2 = sT2[kk];
        float4 v0 = make_float4(e1.x * t1, e1.y * t1,
                                e1.x*t2.x + e1.y*t2.y, e1.x*t2.y - e1.y*t2.x);
        float4 v1 = make_float4(e1.z * t1, e1.w * t1,
                                e1.z*t2.x + e1.w*t2.y, e1.z*t2.y - e1.w*t2.x);
        size_t f0 = (size_t)(b * 2 + 0) * (4 * (size_t)NTRIP) + 4 * (size_t)t;
        size_t f1 = (size_t)(b * 2 + 1) * (4 * (size_t)NTRIP) + 4 * (size_t)t;
        if (f0 + 4 <= cap_f) {
            *reinterpret_cast<float2*>(out + f0)     = make_float2(v0.x, v0.y);
            *reinterpret_cast<float2*>(out + f0 + 2) = make_float2(v0.z, v0.w);
        }
        if (f1 + 4 <= cap_f) {
            *reinterpret_cast<float2*>(out + f1)     = make_float2(v1.x, v1.y);
            *reinterpret_cast<float2*>(out + f1 + 2) = make_float2(v1.z, v1.w);
        }
    }
}

extern "C" void kernel_launch(void* const* d_in, const int* in_sizes, int n_in,
                              void* d_out, int out_size)
{
    if (!d_in || !d_out || n_in < 2) return;
    const float* Er = (const float*)d_in[0];
    const float* Ei = (const float*)d_in[1];
    if (!Er || !Ei) return;
    (void)in_sizes;

    const long long os = (long long)out_size;

    if (os == NCPLX || os == NCPLX * 4) {
        dim3 grid((NJ + JBLK - 1) / JBLK, BATCH);   // 13 x 128
        sofeat_v4_kernel<<<grid, TPB>>>(Er, Ei, (float4*)d_out);
    } else if (os == NFLT || os == NFLT * 4) {
        dim3 grid((NTRIP + TBLK - 1) / TBLK, BATCH);
        sofeat_full_kernel<<<grid, TPB>>>(Er, Ei, (float*)d_out, (size_t)NFLT);
    } else {
        size_t cap = (os > 0) ? (size_t)os : 0;
        if (cap > (size_t)NFLT) cap = (size_t)NFLT;
        dim3 grid((NTRIP + TBLK - 1) / TBLK, BATCH);
        sofeat_full_kernel<<<grid, TPB>>>(Er, Ei, (float*)d_out, cap);
    }
}

// round 9
// speedup vs baseline: 1.0949x; 1.0949x over previous
#include <cuda_runtime.h>
#include <stdint.h>

#define MDIM  41
#define HALF  20
#define NPAIR 1261                 // (m,n) pairs with |m+n| <= 20
#define NTRIP (NPAIR * MDIM)       // 51701 triplets
#define BATCH 128
#define TPB   256
#define TPT   4                    // t per thread
#define TBLK  (TPB * TPT)          // 1024 t per block
#define MAXP  28                   // pairs spanned by a 1024-t window (<=26)
#define NCPLX (26470912LL)         // 128*2*2*51701 (real-parts buffer, floats)
#define NFLT  (52941824LL)         // full interleaved-complex float count

// prefix of pair counts: rows 0..40, count(i) = 41 - |i-20|
__device__ __forceinline__ int pair_base(int i) {
    return (i <= HALF) ? (i * (i + 41)) >> 1
                       : 651 + (((102 - i) * (i - 21)) >> 1);
}

__device__ __forceinline__ void decode_pair(int p, int& im, int& in_, int& imn) {
    int i;
    if (p < 651) {
        i = (int)((-41.0f + __fsqrt_rn(1681.0f + 8.0f * (float)p)) * 0.5f);
    } else {
        float q = (float)(p - 651);
        i = 21 + (int)((81.0f - __fsqrt_rn(6561.0f - 8.0f * q)) * 0.5f);
    }
    if (i < 0) i = 0;
    if (i > 40) i = 40;
    while (i < 40 && pair_base(i + 1) <= p) i++;
    while (i > 0 && pair_base(i) > p) i--;
    int m   = i - HALF;
    int off = p - pair_base(i);
    int nlo = (m > 0) ? -HALF : -HALF - m;
    int n   = nlo + off;
    im  = i;
    in_ = n + HALF;
    imn = m + n + HALF;
}

__device__ __forceinline__ float4 make_e1(const float4* sE, int p) {
    int im, in_, imn;
    decode_pair(p, im, in_, imn);
    float4 a = sE[im], c = sE[in_], d = sE[imn];
    float abx0 = a.x*c.x - a.y*c.y;
    float aby0 = a.x*c.y + a.y*c.x;
    float abx1 = a.z*c.z - a.w*c.w;
    float aby1 = a.z*c.w + a.w*c.z;
    return make_float4(abx0*d.x + aby0*d.y,   // e1x0
                       aby0*d.x - abx0*d.y,   // e1y0
                       abx1*d.z + aby1*d.w,   // e1x1
                       aby1*d.z - abx1*d.w);  // e1y1
}

// ---------------- MODE 1: real-parts-only layout (primary) ----------------
// out as float2: element (b*2+nm)*NTRIP + t = {feat1.re, feat2.re}
__global__ void __launch_bounds__(TPB)
sofeat_kernel(const float* __restrict__ Er,
              const float* __restrict__ Ei,
              float2* __restrict__ out2)
{
    __shared__ float4 sE[MDIM];      // (re0, im0, re1, im1)
    __shared__ float  sT1[MDIM];
    __shared__ float2 sT2[MDIM];
    __shared__ float4 sE1[MAXP];     // (e1x0, e1y0, e1x1, e1y1)

    const int tid  = threadIdx.x;
    const int b    = blockIdx.y;
    const int t_lo = blockIdx.x * TBLK;
    const int t_hi = (t_lo + TBLK < NTRIP) ? t_lo + TBLK : NTRIP;
    const int p_lo = t_lo / MDIM;
    const int np   = (t_hi - 1) / MDIM - p_lo + 1;   // <= 26

    // phase 0: load E[b], compute term1/term2 (threads 0..40)
    if (tid < MDIM) {
        const float* er = Er + (size_t)b * (MDIM * 2);
        const float* ei = Ei + (size_t)b * (MDIM * 2);
        int i = tid, j = 40 - tid;
        float4 e = make_float4(er[2*i], ei[2*i], er[2*i+1], ei[2*i+1]);
        float4 q = make_float4(er[2*j], ei[2*j], er[2*j+1], ei[2*j+1]);
        sE[i]  = e;
        sT1[i] = e.x*e.x + e.y*e.y + e.z*e.z + e.w*e.w;
        float2 t2;
        t2.x = e.x*q.x - e.y*q.y + e.z*q.z - e.w*q.w;
        t2.y = e.x*q.y + e.y*q.x + e.z*q.w + e.w*q.z;
        sT2[i] = t2;
    }
    __syncthreads();

    // phase 1: E1 per pair in this block's window
    if (tid < np)
        sE1[tid] = make_e1(sE, p_lo + tid);
    __syncthreads();

    // phase 2: stream, evict-first stores
    const size_t base0 = (size_t)(b * 2 + 0) * NTRIP;   // float2 elements
    const size_t base1 = (size_t)(b * 2 + 1) * NTRIP;

    int t = t_lo + tid;
    #pragma unroll
    for (int jj = 0; jj < TPT; jj++, t += TPB) {
        if (t >= t_hi) break;

        const unsigned p  = (unsigned)t / MDIM;   // magic-mul division
        const int      kk = t - (int)p * MDIM;

        const float4 e1 = sE1[p - (unsigned)p_lo];
        const float  t1 = sT1[kk];
        const float2 t2 = sT2[kk];

        float2 v0 = make_float2(e1.x * t1, e1.x*t2.x + e1.y*t2.y);
        float2 v1 = make_float2(e1.z * t1, e1.z*t2.x + e1.w*t2.y);
        __stcs(out2 + base0 + t, v0);   // streaming: evict-first in L2
        __stcs(out2 + base1 + t, v1);
    }
}

// ---------------- MODE 0 fallback: interleaved complex ----------------
__global__ void __launch_bounds__(TPB)
sofeat_full_kernel(const float* __restrict__ Er,
                   const float* __restrict__ Ei,
                   float* __restrict__ out,
                   size_t cap_f)
{
    __shared__ float4 sE[MDIM];
    __shared__ float  sT1[MDIM];
    __shared__ float2 sT2[MDIM];
    __shared__ float4 sE1[MAXP];

    const int tid  = threadIdx.x;
    const int b    = blockIdx.y;
    const int t_lo = blockIdx.x * TBLK;
    const int t_hi = (t_lo + TBLK < NTRIP) ? t_lo + TBLK : NTRIP;
    const int p_lo = t_lo / MDIM;
    const int np   = (t_hi - 1) / MDIM - p_lo + 1;

    if (tid < MDIM) {
        const float* er = Er + (size_t)b * (MDIM * 2);
        const float* ei = Ei + (size_t)b * (MDIM * 2);
        int i = tid, j = 40 - tid;
        float4 e = make_float4(er[2*i], ei[2*i], er[2*i+1], ei[2*i+1]);
        float4 q = make_float4(er[2*j], ei[2*j], er[2*j+1], ei[2*j+1]);
        sE[i]  = e;
        sT1[i] = e.x*e.x + e.y*e.y + e.z*e.z + e.w*e.w;
        float2 t2;
        t2.x = e.x*q.x - e.y*q.y + e.z*q.z - e.w*q.w;
        t2.y = e.x*q.y + e.y*q.x + e.z*q.w + e.w*q.z;
        sT2[i] = t2;
    }
    __syncthreads();

    if (tid < np)
        sE1[tid] = make_e1(sE, p_lo + tid);
    __syncthreads();

    int t = t_lo + tid;
    #pragma unroll
    for (int jj = 0; jj < TPT; jj++, t += TPB) {
        if (t >= t_hi) break;
        const unsigned p  = (unsigned)t / MDIM;
        const int      kk = t - (int)p * MDIM;
        const float4 e1 = sE1[p - (unsigned)p_lo];
        const float  t1 = sT1[kk];
        const float2 t2 = sT2[kk];
        float4 v0 = make_float4(e1.x * t1, e1.y * t1,
                                e1.x*t2.x + e1.y*t2.y, e1.x*t2.y - e1.y*t2.x);
        float4 v1 = make_float4(e1.z * t1, e1.w * t1,
                                e1.z*t2.x + e1.w*t2.y, e1.z*t2.y - e1.w*t2.x);
        size_t f0 = (size_t)(b * 2 + 0) * (4 * (size_t)NTRIP) + 4 * (size_t)t;
        size_t f1 = (size_t)(b * 2 + 1) * (4 * (size_t)NTRIP) + 4 * (size_t)t;
        if (f0 + 4 <= cap_f) {
            __stcs(reinterpret_cast<float2*>(out + f0),     make_float2(v0.x, v0.y));
            __stcs(reinterpret_cast<float2*>(out + f0 + 2), make_float2(v0.z, v0.w));
        }
        if (f1 + 4 <= cap_f) {
            __stcs(reinterpret_cast<float2*>(out + f1),     make_float2(v1.x, v1.y));
            __stcs(reinterpret_cast<float2*>(out + f1 + 2), make_float2(v1.z, v1.w));
        }
    }
}

extern "C" void kernel_launch(void* const* d_in, const int* in_sizes, int n_in,
                              void* d_out, int out_size)
{
    if (!d_in || !d_out || n_in < 2) return;
    const float* Er = (const float*)d_in[0];
    const float* Ei = (const float*)d_in[1];
    if (!Er || !Ei) return;
    (void)in_sizes;

    const long long os = (long long)out_size;
    dim3 grid((NTRIP + TBLK - 1) / TBLK, BATCH);

    if (os == NCPLX || os == NCPLX * 4) {
        sofeat_kernel<<<grid, TPB>>>(Er, Ei, (float2*)d_out);
    } else if (os == NFLT || os == NFLT * 4) {
        sofeat_full_kernel<<<grid, TPB>>>(Er, Ei, (float*)d_out, (size_t)NFLT);
    } else {
        size_t cap = (os > 0) ? (size_t)os : 0;
        if (cap > (size_t)NFLT) cap = (size_t)NFLT;
        sofeat_full_kernel<<<grid, TPB>>>(Er, Ei, (float*)d_out, cap);
    }
}

// round 10
// speedup vs baseline: 1.1082x; 1.0122x over previous
#include <cuda_runtime.h>
#include <stdint.h>

#define MDIM  41
#define HALF  20
#define NPAIR 1261                 // (m,n) pairs with |m+n| <= 20
#define NTRIP (NPAIR * MDIM)       // 51701 triplets
#define BATCH 128
#define TPB   256
#define TPT   8                    // t per thread
#define TBLK  (TPB * TPT)          // 2048 t per block
#define MAXP  56                   // pairs spanned by a 2048-t window (<=52)
#define NCPLX (26470912LL)         // 128*2*2*51701 (real-parts buffer, floats)
#define NFLT  (52941824LL)         // full interleaved-complex float count

// prefix of pair counts: rows 0..40, count(i) = 41 - |i-20|
__device__ __forceinline__ int pair_base(int i) {
    return (i <= HALF) ? (i * (i + 41)) >> 1
                       : 651 + (((102 - i) * (i - 21)) >> 1);
}

__device__ __forceinline__ void decode_pair(int p, int& im, int& in_, int& imn) {
    int i;
    if (p < 651) {
        i = (int)((-41.0f + __fsqrt_rn(1681.0f + 8.0f * (float)p)) * 0.5f);
    } else {
        float q = (float)(p - 651);
        i = 21 + (int)((81.0f - __fsqrt_rn(6561.0f - 8.0f * q)) * 0.5f);
    }
    if (i < 0) i = 0;
    if (i > 40) i = 40;
    while (i < 40 && pair_base(i + 1) <= p) i++;
    while (i > 0 && pair_base(i) > p) i--;
    int m   = i - HALF;
    int off = p - pair_base(i);
    int nlo = (m > 0) ? -HALF : -HALF - m;
    int n   = nlo + off;
    im  = i;
    in_ = n + HALF;
    imn = m + n + HALF;
}

__device__ __forceinline__ float4 make_e1(const float4* sE, int p) {
    int im, in_, imn;
    decode_pair(p, im, in_, imn);
    float4 a = sE[im], c = sE[in_], d = sE[imn];
    float abx0 = a.x*c.x - a.y*c.y;
    float aby0 = a.x*c.y + a.y*c.x;
    float abx1 = a.z*c.z - a.w*c.w;
    float aby1 = a.z*c.w + a.w*c.z;
    return make_float4(abx0*d.x + aby0*d.y,   // e1x0
                       aby0*d.x - abx0*d.y,   // e1y0
                       abx1*d.z + aby1*d.w,   // e1x1
                       aby1*d.z - abx1*d.w);  // e1y1
}

// ---------------- MODE 1: real-parts-only layout (primary) ----------------
// out as float2: element (b*2+nm)*NTRIP + t = {feat1.re, feat2.re}
__global__ void __launch_bounds__(TPB)
sofeat_kernel(const float* __restrict__ Er,
              const float* __restrict__ Ei,
              float2* __restrict__ out2)
{
    __shared__ float4 sE[MDIM];      // (re0, im0, re1, im1)
    __shared__ float  sT1[MDIM];
    __shared__ float2 sT2[MDIM];
    __shared__ float4 sE1[MAXP];     // (e1x0, e1y0, e1x1, e1y1)

    const int tid  = threadIdx.x;
    const int b    = blockIdx.y;
    const int t_lo = blockIdx.x * TBLK;
    const int t_hi = (t_lo + TBLK < NTRIP) ? t_lo + TBLK : NTRIP;
    const int p_lo = t_lo / MDIM;
    const int np   = (t_hi - 1) / MDIM - p_lo + 1;   // <= 52

    // phase 0a: vector-load E[b] into shared (threads 0..40, LDG.64 x2)
    if (tid < MDIM) {
        const float2* er2 = reinterpret_cast<const float2*>(Er + (size_t)b * (MDIM * 2));
        const float2* ei2 = reinterpret_cast<const float2*>(Ei + (size_t)b * (MDIM * 2));
        float2 er = er2[tid];        // (re mode0, re mode1)
        float2 ei = ei2[tid];        // (im mode0, im mode1)
        sE[tid] = make_float4(er.x, ei.x, er.y, ei.y);
    }
    __syncthreads();

    // phase 0b: terms from shared (mirror via sE)
    if (tid < MDIM) {
        float4 e = sE[tid];
        float4 q = sE[40 - tid];
        sT1[tid] = e.x*e.x + e.y*e.y + e.z*e.z + e.w*e.w;
        float2 t2;
        t2.x = e.x*q.x - e.y*q.y + e.z*q.z - e.w*q.w;
        t2.y = e.x*q.y + e.y*q.x + e.z*q.w + e.w*q.z;
        sT2[tid] = t2;
    }
    // phase 1 needs sE (ready) — compute E1 per pair in window
    if (tid < np)
        sE1[tid] = make_e1(sE, p_lo + tid);
    __syncthreads();

    // phase 2: stream; p/k via carry increments (no per-iter divide)
    const size_t base0 = (size_t)(b * 2 + 0) * NTRIP;
    const size_t base1 = (size_t)(b * 2 + 1) * NTRIP;

    int t = t_lo + tid;
    unsigned p = (unsigned)t / MDIM;          // one magic-mul divide
    int kk = t - (int)p * MDIM;
    int lp = (int)(p - (unsigned)p_lo);

    #pragma unroll
    for (int jj = 0; jj < TPT; jj++) {
        if (t >= t_hi) break;

        const float4 e1 = sE1[lp];
        const float  t1 = sT1[kk];
        const float2 t2 = sT2[kk];

        float2 v0 = make_float2(e1.x * t1, e1.x*t2.x + e1.y*t2.y);
        float2 v1 = make_float2(e1.z * t1, e1.z*t2.x + e1.w*t2.y);
        out2[base0 + t] = v0;
        out2[base1 + t] = v1;

        // advance t by TPB=256: 256 = 6*41 + 10
        t  += TPB;
        kk += 10;
        lp += 6;
        if (kk >= MDIM) { kk -= MDIM; lp += 1; }
    }
}

// ---------------- MODE 0 fallback: interleaved complex ----------------
#define FTPT  4
#define FTBLK (TPB * FTPT)
#define FMAXP 28
__global__ void __launch_bounds__(TPB)
sofeat_full_kernel(const float* __restrict__ Er,
                   const float* __restrict__ Ei,
                   float* __restrict__ out,
                   size_t cap_f)
{
    __shared__ float4 sE[MDIM];
    __shared__ float  sT1[MDIM];
    __shared__ float2 sT2[MDIM];
    __shared__ float4 sE1[FMAXP];

    const int tid  = threadIdx.x;
    const int b    = blockIdx.y;
    const int t_lo = blockIdx.x * FTBLK;
    const int t_hi = (t_lo + FTBLK < NTRIP) ? t_lo + FTBLK : NTRIP;
    const int p_lo = t_lo / MDIM;
    const int np   = (t_hi - 1) / MDIM - p_lo + 1;

    if (tid < MDIM) {
        const float2* er2 = reinterpret_cast<const float2*>(Er + (size_t)b * (MDIM * 2));
        const float2* ei2 = reinterpret_cast<const float2*>(Ei + (size_t)b * (MDIM * 2));
        float2 er = er2[tid];
        float2 ei = ei2[tid];
        sE[tid] = make_float4(er.x, ei.x, er.y, ei.y);
    }
    __syncthreads();
    if (tid < MDIM) {
        float4 e = sE[tid];
        float4 q = sE[40 - tid];
        sT1[tid] = e.x*e.x + e.y*e.y + e.z*e.z + e.w*e.w;
        float2 t2;
        t2.x = e.x*q.x - e.y*q.y + e.z*q.z - e.w*q.w;
        t2.y = e.x*q.y + e.y*q.x + e.z*q.w + e.w*q.z;
        sT2[tid] = t2;
    }
    if (tid < np)
        sE1[tid] = make_e1(sE, p_lo + tid);
    __syncthreads();

    int t = t_lo + tid;
    #pragma unroll
    for (int jj = 0; jj < FTPT; jj++, t += TPB) {
        if (t >= t_hi) break;
        const unsigned p  = (unsigned)t / MDIM;
        const int      kk = t - (int)p * MDIM;
        const float4 e1 = sE1[p - (unsigned)p_lo];
        const float  t1 = sT1[kk];
        const float2 t2 = sT2[kk];
        float4 v0 = make_float4(e1.x * t1, e1.y * t1,
                                e1.x*t2.x + e1.y*t2.y, e1.x*t2.y - e1.y*t2.x);
        float4 v1 = make_float4(e1.z * t1, e1.w * t1,
                                e1.z*t2.x + e1.w*t2.y, e1.z*t2.y - e1.w*t2.x);
        size_t f0 = (size_t)(b * 2 + 0) * (4 * (size_t)NTRIP) + 4 * (size_t)t;
        size_t f1 = (size_t)(b * 2 + 1) * (4 * (size_t)NTRIP) + 4 * (size_t)t;
        if (f0 + 4 <= cap_f) {
            *reinterpret_cast<float2*>(out + f0)     = make_float2(v0.x, v0.y);
            *reinterpret_cast<float2*>(out + f0 + 2) = make_float2(v0.z, v0.w);
        }
        if (f1 + 4 <= cap_f) {
            *reinterpret_cast<float2*>(out + f1)     = make_float2(v1.x, v1.y);
            *reinterpret_cast<float2*>(out + f1 + 2) = make_float2(v1.z, v1.w);
        }
    }
}

extern "C" void kernel_launch(void* const* d_in, const int* in_sizes, int n_in,
                              void* d_out, int out_size)
{
    if (!d_in || !d_out || n_in < 2) return;
    const float* Er = (const float*)d_in[0];
    const float* Ei = (const float*)d_in[1];
    if (!Er || !Ei) return;
    (void)in_sizes;

    const long long os = (long long)out_size;

    if (os == NCPLX || os == NCPLX * 4) {
        dim3 grid((NTRIP + TBLK - 1) / TBLK, BATCH);   // 26 x 128
        sofeat_kernel<<<grid, TPB>>>(Er, Ei, (float2*)d_out);
    } else if (os == NFLT || os == NFLT * 4) {
        dim3 grid((NTRIP + FTBLK - 1) / FTBLK, BATCH);
        sofeat_full_kernel<<<grid, TPB>>>(Er, Ei, (float*)d_out, (size_t)NFLT);
    } else {
        size_t cap = (os > 0) ? (size_t)os : 0;
        if (cap > (size_t)NFLT) cap = (size_t)NFLT;
        dim3 grid((NTRIP + FTBLK - 1) / FTBLK, BATCH);
        sofeat_full_kernel<<<grid, TPB>>>(Er, Ei, (float*)d_out, cap);
    }
}

// round 11
// speedup vs baseline: 1.1306x; 1.0202x over previous
#include <cuda_runtime.h>
#include <stdint.h>

#define MDIM  41
#define HALF  20
#define NPAIR 1261                 // (m,n) pairs with |m+n| <= 20
#define NTRIP (NPAIR * MDIM)       // 51701 triplets
#define BATCH 128
#define TPB   256
#define TPT   8                    // t per thread
#define TBLK  (TPB * TPT)          // 2048 t per block
#define MAXP  56                   // pairs spanned by a 2048-t window (<=52)
#define NCPLX (26470912LL)         // 128*2*2*51701 (real-parts buffer, floats)
#define NFLT  (52941824LL)         // full interleaved-complex float count

__device__ __forceinline__ int pair_base(int i) {
    return (i <= HALF) ? (i * (i + 41)) >> 1
                       : 651 + (((102 - i) * (i - 21)) >> 1);
}

__device__ __forceinline__ void decode_pair(int p, int& im, int& in_, int& imn) {
    int i;
    if (p < 651) {
        i = (int)((-41.0f + __fsqrt_rn(1681.0f + 8.0f * (float)p)) * 0.5f);
    } else {
        float q = (float)(p - 651);
        i = 21 + (int)((81.0f - __fsqrt_rn(6561.0f - 8.0f * q)) * 0.5f);
    }
    if (i < 0) i = 0;
    if (i > 40) i = 40;
    while (i < 40 && pair_base(i + 1) <= p) i++;
    while (i > 0 && pair_base(i) > p) i--;
    int m   = i - HALF;
    int off = p - pair_base(i);
    int nlo = (m > 0) ? -HALF : -HALF - m;
    int n   = nlo + off;
    im  = i;
    in_ = n + HALF;
    imn = m + n + HALF;
}

__device__ __forceinline__ float4 make_e1(const float4* sE, int p) {
    int im, in_, imn;
    decode_pair(p, im, in_, imn);
    float4 a = sE[im], c = sE[in_], d = sE[imn];
    float abx0 = a.x*c.x - a.y*c.y;
    float aby0 = a.x*c.y + a.y*c.x;
    float abx1 = a.z*c.z - a.w*c.w;
    float aby1 = a.z*c.w + a.w*c.z;
    return make_float4(abx0*d.x + aby0*d.y,   // e1x0
                       aby0*d.x - abx0*d.y,   // e1y0
                       abx1*d.z + aby1*d.w,   // e1x1
                       aby1*d.z - abx1*d.w);  // e1y1
}

// ---------------- MODE 1: real-parts-only layout (primary) ----------------
// out as float2: element (b*2+nm)*NTRIP + t = {feat1.re, feat2.re}
__global__ void __launch_bounds__(TPB)
sofeat_kernel(const float* __restrict__ Er,
              const float* __restrict__ Ei,
              float2* __restrict__ out2)
{
    __shared__ float4 sE[MDIM];      // (re0, im0, re1, im1)
    __shared__ float  sT1[MDIM];
    __shared__ float2 sT2[MDIM];
    __shared__ float4 sE1[MAXP];     // (e1x0, e1y0, e1x1, e1y1)

    const int tid  = threadIdx.x;
    const int b    = blockIdx.y;
    const int t_lo = blockIdx.x * TBLK;
    const int t_hi = (t_lo + TBLK < NTRIP) ? t_lo + TBLK : NTRIP;
    const int p_lo = t_lo / MDIM;
    const int np   = (t_hi - 1) / MDIM - p_lo + 1;   // <= 52

    // phase 0a: vector-load E[b] into shared
    if (tid < MDIM) {
        const float2* er2 = reinterpret_cast<const float2*>(Er + (size_t)b * (MDIM * 2));
        const float2* ei2 = reinterpret_cast<const float2*>(Ei + (size_t)b * (MDIM * 2));
        float2 er = er2[tid];
        float2 ei = ei2[tid];
        sE[tid] = make_float4(er.x, ei.x, er.y, ei.y);
    }
    __syncthreads();

    // phase 0b: terms; phase 1: E1 per pair
    if (tid < MDIM) {
        float4 e = sE[tid];
        float4 q = sE[40 - tid];
        sT1[tid] = e.x*e.x + e.y*e.y + e.z*e.z + e.w*e.w;
        float2 t2;
        t2.x = e.x*q.x - e.y*q.y + e.z*q.z - e.w*q.w;
        t2.y = e.x*q.y + e.y*q.x + e.z*q.w + e.w*q.z;
        sT2[tid] = t2;
    }
    if (tid < np)
        sE1[tid] = make_e1(sE, p_lo + tid);
    __syncthreads();

    const size_t base0 = (size_t)(b * 2 + 0) * NTRIP;
    const size_t base1 = (size_t)(b * 2 + 1) * NTRIP;

    const int t0 = t_lo + tid;
    const unsigned pp = (unsigned)t0 / MDIM;      // one divide
    const int kk0 = t0 - (int)pp * MDIM;
    const int lp0 = (int)(pp - (unsigned)p_lo);

    if (t_lo + TBLK <= NTRIP) {
        // FULL block: guard-free, independent per-iteration addressing
        #pragma unroll
        for (int jj = 0; jj < TPT; jj++) {
            int kkj = kk0 + 10 * jj;             // 256 = 6*41 + 10
            int lpj = lp0 + 6 * jj;
            if (kkj >= 2 * MDIM)      { kkj -= 2 * MDIM; lpj += 2; }
            else if (kkj >= MDIM)     { kkj -= MDIM;     lpj += 1; }

            const float4 e1 = sE1[lpj];
            const float  t1 = sT1[kkj];
            const float2 t2 = sT2[kkj];

            const int t = t0 + jj * TPB;
            out2[base0 + t] = make_float2(e1.x * t1, e1.x*t2.x + e1.y*t2.y);
            out2[base1 + t] = make_float2(e1.z * t1, e1.z*t2.x + e1.w*t2.y);
        }
    } else {
        // TAIL block (one per batch): guarded
        #pragma unroll
        for (int jj = 0; jj < TPT; jj++) {
            const int t = t0 + jj * TPB;
            if (t >= NTRIP) break;
            int kkj = kk0 + 10 * jj;
            int lpj = lp0 + 6 * jj;
            if (kkj >= 2 * MDIM)      { kkj -= 2 * MDIM; lpj += 2; }
            else if (kkj >= MDIM)     { kkj -= MDIM;     lpj += 1; }

            const float4 e1 = sE1[lpj];
            const float  t1 = sT1[kkj];
            const float2 t2 = sT2[kkj];
            out2[base0 + t] = make_float2(e1.x * t1, e1.x*t2.x + e1.y*t2.y);
            out2[base1 + t] = make_float2(e1.z * t1, e1.z*t2.x + e1.w*t2.y);
        }
    }
}

// ---------------- MODE 0 fallback: interleaved complex ----------------
#define FTPT  4
#define FTBLK (TPB * FTPT)
#define FMAXP 28
__global__ void __launch_bounds__(TPB)
sofeat_full_kernel(const float* __restrict__ Er,
                   const float* __restrict__ Ei,
                   float* __restrict__ out,
                   size_t cap_f)
{
    __shared__ float4 sE[MDIM];
    __shared__ float  sT1[MDIM];
    __shared__ float2 sT2[MDIM];
    __shared__ float4 sE1[FMAXP];

    const int tid  = threadIdx.x;
    const int b    = blockIdx.y;
    const int t_lo = blockIdx.x * FTBLK;
    const int t_hi = (t_lo + FTBLK < NTRIP) ? t_lo + FTBLK : NTRIP;
    const int p_lo = t_lo / MDIM;
    const int np   = (t_hi - 1) / MDIM - p_lo + 1;

    if (tid < MDIM) {
        const float2* er2 = reinterpret_cast<const float2*>(Er + (size_t)b * (MDIM * 2));
        const float2* ei2 = reinterpret_cast<const float2*>(Ei + (size_t)b * (MDIM * 2));
        float2 er = er2[tid];
        float2 ei = ei2[tid];
        sE[tid] = make_float4(er.x, ei.x, er.y, ei.y);
    }
    __syncthreads();
    if (tid < MDIM) {
        float4 e = sE[tid];
        float4 q = sE[40 - tid];
        sT1[tid] = e.x*e.x + e.y*e.y + e.z*e.z + e.w*e.w;
        float2 t2;
        t2.x = e.x*q.x - e.y*q.y + e.z*q.z - e.w*q.w;
        t2.y = e.x*q.y + e.y*q.x + e.z*q.w + e.w*q.z;
        sT2[tid] = t2;
    }
    if (tid < np)
        sE1[tid] = make_e1(sE, p_lo + tid);
    __syncthreads();

    int t = t_lo + tid;
    #pragma unroll
    for (int jj = 0; jj < FTPT; jj++, t += TPB) {
        if (t >= t_hi) break;
        const unsigned p  = (unsigned)t / MDIM;
        const int      kk = t - (int)p * MDIM;
        const float4 e1 = sE1[p - (unsigned)p_lo];
        const float  t1 = sT1[kk];
        const float2 t2 = sT2[kk];
        float4 v0 = make_float4(e1.x * t1, e1.y * t1,
                                e1.x*t2.x + e1.y*t2.y, e1.x*t2.y - e1.y*t2.x);
        float4 v1 = make_float4(e1.z * t1, e1.w * t1,
                                e1.z*t2.x + e1.w*t2.y, e1.z*t2.y - e1.w*t2.x);
        size_t f0 = (size_t)(b * 2 + 0) * (4 * (size_t)NTRIP) + 4 * (size_t)t;
        size_t f1 = (size_t)(b * 2 + 1) * (4 * (size_t)NTRIP) + 4 * (size_t)t;
        if (f0 + 4 <= cap_f) {
            *reinterpret_cast<float2*>(out + f0)     = make_float2(v0.x, v0.y);
            *reinterpret_cast<float2*>(out + f0 + 2) = make_float2(v0.z, v0.w);
        }
        if (f1 + 4 <= cap_f) {
            *reinterpret_cast<float2*>(out + f1)     = make_float2(v1.x, v1.y);
            *reinterpret_cast<float2*>(out + f1 + 2) = make_float2(v1.z, v1.w);
        }
    }
}

extern "C" void kernel_launch(void* const* d_in, const int* in_sizes, int n_in,
                              void* d_out, int out_size)
{
    if (!d_in || !d_out || n_in < 2) return;
    const float* Er = (const float*)d_in[0];
    const float* Ei = (const float*)d_in[1];
    if (!Er || !Ei) return;
    (void)in_sizes;

    const long long os = (long long)out_size;

    if (os == NCPLX || os == NCPLX * 4) {
        dim3 grid((NTRIP + TBLK - 1) / TBLK, BATCH);   // 26 x 128
        sofeat_kernel<<<grid, TPB>>>(Er, Ei, (float2*)d_out);
    } else if (os == NFLT || os == NFLT * 4) {
        dim3 grid((NTRIP + FTBLK - 1) / FTBLK, BATCH);
        sofeat_full_kernel<<<grid, TPB>>>(Er, Ei, (float*)d_out, (size_t)NFLT);
    } else {
        size_t cap = (os > 0) ? (size_t)os : 0;
        if (cap > (size_t)NFLT) cap = (size_t)NFLT;
        dim3 grid((NTRIP + FTBLK - 1) / FTBLK, BATCH);
        sofeat_full_kernel<<<grid, TPB>>>(Er, Ei, (float*)d_out, cap);
    }
}